// round 1
// baseline (speedup 1.0000x reference)
#include <cuda_runtime.h>

// Problem constants (fixed by the reference setup)
#define BB   2
#define CH   64
#define NH   8
#define DH   8
#define HW   48
#define LL   2304            // HW*HW
#define BCHL (BB*CH*LL)      // 294912

// Scratch (device globals — no allocation allowed)
__device__ float g_q [BCHL];
__device__ float g_k [BCHL];
__device__ float g_vp[BCHL];   // v, then scaled in-place by 1/Z
__device__ float g_o [BCHL];

// ---------------------------------------------------------------------------
// K1: fused q/k/v 1x1 convs.  grid = 144 blocks x 256 thr.
// Each block: 32 columns; thread (lane = tid&31 -> column, og = tid>>5 -> 8 out rows)
// q is scaled by d^-0.5 and ALSO written to the q-output region of d_out.
// ---------------------------------------------------------------------------
__global__ __launch_bounds__(256) void k_qkv(
    const float* __restrict__ x,
    const float* __restrict__ Wq, const float* __restrict__ bq,
    const float* __restrict__ Wk, const float* __restrict__ bk,
    const float* __restrict__ Wv, const float* __restrict__ bv,
    float* __restrict__ q_out)
{
    __shared__ __align__(16) float sW[3][64*64];
    __shared__ float sb[3][64];
    const int tid = threadIdx.x;
    for (int i = tid; i < 4096; i += 256) {
        sW[0][i] = Wq[i]; sW[1][i] = Wk[i]; sW[2][i] = Wv[i];
    }
    if (tid < 64) { sb[0][tid] = bq[tid]; sb[1][tid] = bk[tid]; sb[2][tid] = bv[tid]; }
    __syncthreads();

    const int col = blockIdx.x * 32 + (tid & 31);     // 0..4607
    const int og  = tid >> 5;                          // 0..7
    const int b   = col / LL;
    const int l   = col - b * LL;

    const float* xp = x + (size_t)b * CH * LL + l;
    float xr[64];
#pragma unroll
    for (int c = 0; c < 64; c++) xr[c] = xp[c * LL];

    const float qscale = 0.35355339059327373f;  // 8^-0.5

#pragma unroll
    for (int m = 0; m < 3; m++) {
        float* dst = (m == 0) ? g_q : (m == 1) ? g_k : g_vp;
        const float scale = (m == 0) ? qscale : 1.0f;
#pragma unroll
        for (int j = 0; j < 8; j++) {
            const int o = og * 8 + j;
            const float4* wr = (const float4*)&sW[m][o * 64];
            float a0 = 0.f, a1 = 0.f, a2 = 0.f, a3 = 0.f;
#pragma unroll
            for (int c4 = 0; c4 < 16; c4++) {
                float4 w = wr[c4];
                a0 = fmaf(w.x, xr[c4*4+0], a0);
                a1 = fmaf(w.y, xr[c4*4+1], a1);
                a2 = fmaf(w.z, xr[c4*4+2], a2);
                a3 = fmaf(w.w, xr[c4*4+3], a3);
            }
            float r = ((a0 + a1) + (a2 + a3) + sb[m][o]) * scale;
            const size_t idx = ((size_t)b * CH + o) * LL + l;
            dst[idx] = r;
            if (m == 0) q_out[idx] = r;   // reference returns the SCALED q
        }
    }
}

// ---------------------------------------------------------------------------
// K2 (pass A): Z[k] = sum_q exp(q·k); then v'[c,k] = v[c,k]/Z[k] in-place.
// grid = (16 heads, 9 k-tiles) x 256 thr; thread <-> one k column.
// Q streamed through SMEM in 128-wide tiles, row layout [qq][12] for LDS.128.
// ---------------------------------------------------------------------------
__global__ __launch_bounds__(256) void k_passA()
{
    const int bh = blockIdx.x;
    const int b = bh >> 3, h = bh & 7;
    const int k = blockIdx.y * 256 + threadIdx.x;

    const float* Kb = g_k + (size_t)(b * CH + h * DH) * LL;
    const float* Qb = g_q + (size_t)(b * CH + h * DH) * LL;

    float kd[8];
#pragma unroll
    for (int d = 0; d < 8; d++) kd[d] = Kb[d * LL + k];

    __shared__ __align__(16) float qs[128][12];

    float Z0 = 0.f, Z1 = 0.f;
    for (int q0 = 0; q0 < LL; q0 += 128) {
        __syncthreads();
        for (int i = threadIdx.x; i < 1024; i += 256) {
            const int d = i >> 7, qq = i & 127;
            qs[qq][d] = Qb[d * LL + q0 + qq];
        }
        __syncthreads();
#pragma unroll 4
        for (int qq = 0; qq < 128; qq += 2) {
            const float4* r0 = (const float4*)qs[qq];
            float4 a = r0[0], c = r0[1];
            float l0 = fmaf(c.w, kd[7], fmaf(c.z, kd[6], fmaf(c.y, kd[5], fmaf(c.x, kd[4],
                       fmaf(a.w, kd[3], fmaf(a.z, kd[2], fmaf(a.y, kd[1], a.x * kd[0])))))));
            const float4* r1 = (const float4*)qs[qq + 1];
            float4 a2 = r1[0], c2 = r1[1];
            float l1 = fmaf(c2.w, kd[7], fmaf(c2.z, kd[6], fmaf(c2.y, kd[5], fmaf(c2.x, kd[4],
                       fmaf(a2.w, kd[3], fmaf(a2.z, kd[2], fmaf(a2.y, kd[1], a2.x * kd[0])))))));
            Z0 += __expf(l0);
            Z1 += __expf(l1);
        }
    }
    const float inv = 1.0f / (Z0 + Z1);
    float* Vb = g_vp + (size_t)(b * CH + h * DH) * LL;
#pragma unroll
    for (int d = 0; d < 8; d++) Vb[d * LL + k] *= inv;
}

// ---------------------------------------------------------------------------
// K3 (pass B): o[c,q] = sum_k v'[c,k] * exp(q·k).
// grid = (16 heads, 9 q-tiles) x 256 thr; thread <-> one q column.
// K and V' streamed through SMEM in 128-wide tiles.
// ---------------------------------------------------------------------------
__global__ __launch_bounds__(256) void k_passB()
{
    const int bh = blockIdx.x;
    const int b = bh >> 3, h = bh & 7;
    const int q = blockIdx.y * 256 + threadIdx.x;

    const float* Qb = g_q  + (size_t)(b * CH + h * DH) * LL;
    const float* Kb = g_k  + (size_t)(b * CH + h * DH) * LL;
    const float* Vb = g_vp + (size_t)(b * CH + h * DH) * LL;

    float qd[8];
#pragma unroll
    for (int d = 0; d < 8; d++) qd[d] = Qb[d * LL + q];

    float o[8];
#pragma unroll
    for (int d = 0; d < 8; d++) o[d] = 0.f;

    __shared__ __align__(16) float ks [128][12];
    __shared__ __align__(16) float vsm[128][12];

    for (int k0 = 0; k0 < LL; k0 += 128) {
        __syncthreads();
        for (int i = threadIdx.x; i < 1024; i += 256) {
            const int d = i >> 7, kk = i & 127;
            ks [kk][d] = Kb[d * LL + k0 + kk];
            vsm[kk][d] = Vb[d * LL + k0 + kk];
        }
        __syncthreads();
#pragma unroll 2
        for (int kk = 0; kk < 128; kk++) {
            const float4* kr = (const float4*)ks[kk];
            float4 ka = kr[0], kb = kr[1];
            float l = fmaf(kb.w, qd[7], fmaf(kb.z, qd[6], fmaf(kb.y, qd[5], fmaf(kb.x, qd[4],
                      fmaf(ka.w, qd[3], fmaf(ka.z, qd[2], fmaf(ka.y, qd[1], ka.x * qd[0])))))));
            const float w = __expf(l);
            const float4* vr = (const float4*)vsm[kk];
            float4 va = vr[0], vb = vr[1];
            o[0] = fmaf(w, va.x, o[0]);
            o[1] = fmaf(w, va.y, o[1]);
            o[2] = fmaf(w, va.z, o[2]);
            o[3] = fmaf(w, va.w, o[3]);
            o[4] = fmaf(w, vb.x, o[4]);
            o[5] = fmaf(w, vb.y, o[5]);
            o[6] = fmaf(w, vb.z, o[6]);
            o[7] = fmaf(w, vb.w, o[7]);
        }
    }
    float* Ob = g_o + (size_t)(b * CH + h * DH) * LL;
#pragma unroll
    for (int d = 0; d < 8; d++) Ob[d * LL + q] = o[d];
}

// ---------------------------------------------------------------------------
// K4: output 1x1 conv: out[o,l] = Wo[o,:]·g_o[:,l] + bo[o]
// ---------------------------------------------------------------------------
__global__ __launch_bounds__(256) void k_oconv(
    const float* __restrict__ Wo, const float* __restrict__ bo,
    float* __restrict__ out)
{
    __shared__ __align__(16) float sW[64*64];
    __shared__ float sb[64];
    const int tid = threadIdx.x;
    for (int i = tid; i < 4096; i += 256) sW[i] = Wo[i];
    if (tid < 64) sb[tid] = bo[tid];
    __syncthreads();

    const int col = blockIdx.x * 32 + (tid & 31);
    const int og  = tid >> 5;
    const int b   = col / LL;
    const int l   = col - b * LL;

    const float* xp = g_o + (size_t)b * CH * LL + l;
    float xr[64];
#pragma unroll
    for (int c = 0; c < 64; c++) xr[c] = xp[c * LL];

#pragma unroll
    for (int j = 0; j < 8; j++) {
        const int o = og * 8 + j;
        const float4* wr = (const float4*)&sW[o * 64];
        float a0 = 0.f, a1 = 0.f, a2 = 0.f, a3 = 0.f;
#pragma unroll
        for (int c4 = 0; c4 < 16; c4++) {
            float4 w = wr[c4];
            a0 = fmaf(w.x, xr[c4*4+0], a0);
            a1 = fmaf(w.y, xr[c4*4+1], a1);
            a2 = fmaf(w.z, xr[c4*4+2], a2);
            a3 = fmaf(w.w, xr[c4*4+3], a3);
        }
        out[((size_t)b * CH + o) * LL + l] = (a0 + a1) + (a2 + a3) + sb[o];
    }
}

// ---------------------------------------------------------------------------
extern "C" void kernel_launch(void* const* d_in, const int* in_sizes, int n_in,
                              void* d_out, int out_size)
{
    const float* x  = (const float*)d_in[0];
    const float* Wq = (const float*)d_in[1];
    const float* bq = (const float*)d_in[2];
    const float* Wk = (const float*)d_in[3];
    const float* bk = (const float*)d_in[4];
    const float* Wv = (const float*)d_in[5];
    const float* bv = (const float*)d_in[6];
    const float* Wo = (const float*)d_in[7];
    const float* bo = (const float*)d_in[8];

    float* out   = (float*)d_out;           // first output: conv result
    float* q_out = (float*)d_out + BCHL;    // second output: scaled q

    k_qkv<<<144, 256>>>(x, Wq, bq, Wk, bk, Wv, bv, q_out);
    k_passA<<<dim3(16, 9), 256>>>();
    k_passB<<<dim3(16, 9), 256>>>();
    k_oconv<<<144, 256>>>(Wo, bo, out);
}

// round 2
// speedup vs baseline: 1.9091x; 1.9091x over previous
#include <cuda_runtime.h>

// Problem constants (fixed by the reference setup)
#define BB   2
#define CH   64
#define NH   8
#define DH   8
#define HW   48
#define LL   2304            // HW*HW
#define BCHL (BB*CH*LL)      // 294912
#define SEGS 8
#define QSEG 288             // LL/SEGS
#define KSEG 288

#define LOG2E 1.4426950408889634f

// Packed f32x2 helpers (sm_103a FFMA2 path)
#define FMA2(d,a,b,c) asm("fma.rn.f32x2 %0,%1,%2,%3;" : "=l"(d) : "l"(a), "l"(b), "l"(c))
#define MUL2(d,a,b)   asm("mul.rn.f32x2 %0,%1,%2;"    : "=l"(d) : "l"(a), "l"(b))
#define ADD2(d,a,b)   asm("add.rn.f32x2 %0,%1,%2;"    : "=l"(d) : "l"(a), "l"(b))
#define PACK2(d,x,y)  asm("mov.b64 %0,{%1,%2};"        : "=l"(d) : "f"(x), "f"(y))
#define UNPACK2(x,y,d) asm("mov.b64 {%0,%1},%2;"       : "=f"(x), "=f"(y) : "l"(d))
#define EX2F(r,x)     asm("ex2.approx.ftz.f32 %0,%1;"  : "=f"(r) : "f"(x))

typedef unsigned long long u64;

// Scratch (device globals — no allocation allowed)
__device__ float g_q [BCHL];          // q * d^-0.5 * log2(e)  (for EX2)
__device__ float g_k [BCHL];
__device__ float g_vp[BCHL];          // v, then scaled in-place by 1/Z
__device__ float g_o [BCHL];
__device__ float g_Z [SEGS][BB*NH][LL];
__device__ float g_op[SEGS][BCHL];

// ---------------------------------------------------------------------------
// K1: fused q/k/v 1x1 convs.  grid = 144 blocks x 256 thr.
// ---------------------------------------------------------------------------
__global__ __launch_bounds__(256) void k_qkv(
    const float* __restrict__ x,
    const float* __restrict__ Wq, const float* __restrict__ bq,
    const float* __restrict__ Wk, const float* __restrict__ bk,
    const float* __restrict__ Wv, const float* __restrict__ bv,
    float* __restrict__ q_out)
{
    __shared__ __align__(16) float sW[3][64*64];
    __shared__ float sb[3][64];
    const int tid = threadIdx.x;
    for (int i = tid; i < 4096; i += 256) {
        sW[0][i] = Wq[i]; sW[1][i] = Wk[i]; sW[2][i] = Wv[i];
    }
    if (tid < 64) { sb[0][tid] = bq[tid]; sb[1][tid] = bk[tid]; sb[2][tid] = bv[tid]; }
    __syncthreads();

    const int col = blockIdx.x * 32 + (tid & 31);     // 0..4607
    const int og  = tid >> 5;                          // 0..7
    const int b   = col / LL;
    const int l   = col - b * LL;

    const float* xp = x + (size_t)b * CH * LL + l;
    float xr[64];
#pragma unroll
    for (int c = 0; c < 64; c++) xr[c] = xp[c * LL];

    const float qscale = 0.35355339059327373f;  // 8^-0.5

#pragma unroll
    for (int m = 0; m < 3; m++) {
        float* dst = (m == 0) ? g_q : (m == 1) ? g_k : g_vp;
#pragma unroll
        for (int j = 0; j < 8; j++) {
            const int o = og * 8 + j;
            const float4* wr = (const float4*)&sW[m][o * 64];
            float a0 = 0.f, a1 = 0.f, a2 = 0.f, a3 = 0.f;
#pragma unroll
            for (int c4 = 0; c4 < 16; c4++) {
                float4 w = wr[c4];
                a0 = fmaf(w.x, xr[c4*4+0], a0);
                a1 = fmaf(w.y, xr[c4*4+1], a1);
                a2 = fmaf(w.z, xr[c4*4+2], a2);
                a3 = fmaf(w.w, xr[c4*4+3], a3);
            }
            float r = (a0 + a1) + (a2 + a3) + sb[m][o];
            const size_t idx = ((size_t)b * CH + o) * LL + l;
            if (m == 0) {
                float rq = r * qscale;
                q_out[idx] = rq;                 // reference returns the SCALED q
                dst[idx]   = rq * LOG2E;         // internal: prescaled for EX2
            } else {
                dst[idx] = r;
            }
        }
    }
}

// ---------------------------------------------------------------------------
// K2 (pass A): partial Z over a q-segment.  Each thread owns 4 k columns,
// packed as 2 f32x2 pairs. Q rows stored DUPLICATED in SMEM so the whole
// dot-product chain is packed FFMA2.
// grid = (bh=16, ktile=2, seg=8) x 288 thr.
// ---------------------------------------------------------------------------
__global__ __launch_bounds__(288) void k_passA()
{
    const int bh = blockIdx.x;
    const int b = bh >> 3, h = bh & 7;
    const int tid = threadIdx.x;
    const int k0 = blockIdx.y * 1152 + tid * 4;
    const int seg = blockIdx.z;

    const float* Kb = g_k + (size_t)(b * CH + h * DH) * LL;
    const float* Qb = g_q + (size_t)(b * CH + h * DH) * LL;

    u64 kp0[8], kp1[8];
#pragma unroll
    for (int d = 0; d < 8; d++) {
        float4 kv = *(const float4*)&Kb[d * LL + k0];
        PACK2(kp0[d], kv.x, kv.y);
        PACK2(kp1[d], kv.z, kv.w);
    }

    __shared__ __align__(16) float2 sq[QSEG][8];
    const int q0 = seg * QSEG;
    for (int i = tid; i < QSEG * 8; i += 288) {
        const int d = i / QSEG, qq = i - d * QSEG;
        float v = Qb[d * LL + q0 + qq];
        sq[qq][d] = make_float2(v, v);
    }
    __syncthreads();

    u64 Z0 = 0ull, Z1 = 0ull;   // packed {0,0}
#pragma unroll 2
    for (int qq = 0; qq < QSEG; qq++) {
        const ulonglong2* qr = (const ulonglong2*)sq[qq];
        ulonglong2 qa = qr[0], qb_ = qr[1], qc = qr[2], qd = qr[3];
        u64 l0, l1;
        MUL2(l0, qa.x,  kp0[0]); FMA2(l0, qa.y,  kp0[1], l0);
        FMA2(l0, qb_.x, kp0[2], l0); FMA2(l0, qb_.y, kp0[3], l0);
        FMA2(l0, qc.x,  kp0[4], l0); FMA2(l0, qc.y,  kp0[5], l0);
        FMA2(l0, qd.x,  kp0[6], l0); FMA2(l0, qd.y,  kp0[7], l0);
        MUL2(l1, qa.x,  kp1[0]); FMA2(l1, qa.y,  kp1[1], l1);
        FMA2(l1, qb_.x, kp1[2], l1); FMA2(l1, qb_.y, kp1[3], l1);
        FMA2(l1, qc.x,  kp1[4], l1); FMA2(l1, qc.y,  kp1[5], l1);
        FMA2(l1, qd.x,  kp1[6], l1); FMA2(l1, qd.y,  kp1[7], l1);
        float a0, a1, b0, b1, e0, e1, e2, e3;
        UNPACK2(a0, a1, l0);
        UNPACK2(b0, b1, l1);
        EX2F(e0, a0); EX2F(e1, a1); EX2F(e2, b0); EX2F(e3, b1);
        u64 w0, w1;
        PACK2(w0, e0, e1);
        PACK2(w1, e2, e3);
        ADD2(Z0, Z0, w0);
        ADD2(Z1, Z1, w1);
    }
    float z0, z1, z2, z3;
    UNPACK2(z0, z1, Z0);
    UNPACK2(z2, z3, Z1);
    *(float4*)&g_Z[seg][bh][k0] = make_float4(z0, z1, z2, z3);
}

// ---------------------------------------------------------------------------
// K3: sum Z partials, scale v by 1/Z.  One thread per k column.
// ---------------------------------------------------------------------------
__global__ __launch_bounds__(256) void k_scaleV()
{
    const int t = blockIdx.x * 256 + threadIdx.x;  // 0..36863
    const int bh = t / LL, k = t - bh * LL;
    float z = 0.f;
#pragma unroll
    for (int s = 0; s < SEGS; s++) z += g_Z[s][bh][k];
    const float inv = 1.0f / z;
    const int b = bh >> 3, h = bh & 7;
    float* Vb = g_vp + (size_t)(b * CH + h * DH) * LL + k;
#pragma unroll
    for (int d = 0; d < 8; d++) Vb[d * LL] *= inv;
}

// ---------------------------------------------------------------------------
// K4 (pass B): partial o over a k-segment.  Each thread owns 4 q columns
// (2 packed pairs).  K and V' rows stored DUPLICATED in SMEM; logit chain
// and output accumulation are all packed FFMA2.
// grid = (bh=16, qtile=2, seg=8) x 288 thr.
// ---------------------------------------------------------------------------
__global__ __launch_bounds__(288) void k_passB()
{
    const int bh = blockIdx.x;
    const int b = bh >> 3, h = bh & 7;
    const int tid = threadIdx.x;
    const int q0 = blockIdx.y * 1152 + tid * 4;
    const int seg = blockIdx.z;

    const float* Qb = g_q  + (size_t)(b * CH + h * DH) * LL;
    const float* Kb = g_k  + (size_t)(b * CH + h * DH) * LL;
    const float* Vb = g_vp + (size_t)(b * CH + h * DH) * LL;

    u64 qp0[8], qp1[8];
#pragma unroll
    for (int d = 0; d < 8; d++) {
        float4 qv = *(const float4*)&Qb[d * LL + q0];
        PACK2(qp0[d], qv.x, qv.y);
        PACK2(qp1[d], qv.z, qv.w);
    }

    __shared__ __align__(16) float2 sk[KSEG][8];
    __shared__ __align__(16) float2 sv[KSEG][8];
    const int kb = seg * KSEG;
    for (int i = tid; i < KSEG * 8; i += 288) {
        const int d = i / KSEG, kk = i - d * KSEG;
        float kval = Kb[d * LL + kb + kk];
        float vval = Vb[d * LL + kb + kk];
        sk[kk][d] = make_float2(kval, kval);
        sv[kk][d] = make_float2(vval, vval);
    }
    __syncthreads();

    u64 o0[8], o1[8];
#pragma unroll
    for (int d = 0; d < 8; d++) { o0[d] = 0ull; o1[d] = 0ull; }

#pragma unroll 2
    for (int kk = 0; kk < KSEG; kk++) {
        const ulonglong2* kr = (const ulonglong2*)sk[kk];
        ulonglong2 ka = kr[0], kb_ = kr[1], kc = kr[2], kd = kr[3];
        u64 l0, l1;
        MUL2(l0, qp0[0], ka.x);  FMA2(l0, qp0[1], ka.y,  l0);
        FMA2(l0, qp0[2], kb_.x, l0); FMA2(l0, qp0[3], kb_.y, l0);
        FMA2(l0, qp0[4], kc.x,  l0); FMA2(l0, qp0[5], kc.y,  l0);
        FMA2(l0, qp0[6], kd.x,  l0); FMA2(l0, qp0[7], kd.y,  l0);
        MUL2(l1, qp1[0], ka.x);  FMA2(l1, qp1[1], ka.y,  l1);
        FMA2(l1, qp1[2], kb_.x, l1); FMA2(l1, qp1[3], kb_.y, l1);
        FMA2(l1, qp1[4], kc.x,  l1); FMA2(l1, qp1[5], kc.y,  l1);
        FMA2(l1, qp1[6], kd.x,  l1); FMA2(l1, qp1[7], kd.y,  l1);
        float a0, a1, b0, b1, e0, e1, e2, e3;
        UNPACK2(a0, a1, l0);
        UNPACK2(b0, b1, l1);
        EX2F(e0, a0); EX2F(e1, a1); EX2F(e2, b0); EX2F(e3, b1);
        u64 w0, w1;
        PACK2(w0, e0, e1);
        PACK2(w1, e2, e3);
        const ulonglong2* vr = (const ulonglong2*)sv[kk];
        ulonglong2 va = vr[0], vb_ = vr[1], vc = vr[2], vd = vr[3];
        FMA2(o0[0], w0, va.x,  o0[0]); FMA2(o1[0], w1, va.x,  o1[0]);
        FMA2(o0[1], w0, va.y,  o0[1]); FMA2(o1[1], w1, va.y,  o1[1]);
        FMA2(o0[2], w0, vb_.x, o0[2]); FMA2(o1[2], w1, vb_.x, o1[2]);
        FMA2(o0[3], w0, vb_.y, o0[3]); FMA2(o1[3], w1, vb_.y, o1[3]);
        FMA2(o0[4], w0, vc.x,  o0[4]); FMA2(o1[4], w1, vc.x,  o1[4]);
        FMA2(o0[5], w0, vc.y,  o0[5]); FMA2(o1[5], w1, vc.y,  o1[5]);
        FMA2(o0[6], w0, vd.x,  o0[6]); FMA2(o1[6], w1, vd.x,  o1[6]);
        FMA2(o0[7], w0, vd.y,  o0[7]); FMA2(o1[7], w1, vd.y,  o1[7]);
    }

    float* Ob = g_op[seg] + (size_t)(b * CH + h * DH) * LL;
#pragma unroll
    for (int d = 0; d < 8; d++) {
        float x0, x1, x2, x3;
        UNPACK2(x0, x1, o0[d]);
        UNPACK2(x2, x3, o1[d]);
        *(float4*)&Ob[d * LL + q0] = make_float4(x0, x1, x2, x3);
    }
}

// ---------------------------------------------------------------------------
// K5: reduce o partials across the 8 k-segments.
// ---------------------------------------------------------------------------
__global__ __launch_bounds__(256) void k_reduce()
{
    const int i = blockIdx.x * 256 + threadIdx.x;  // over BCHL/4 = 73728
    float4 a = ((const float4*)g_op[0])[i];
#pragma unroll
    for (int s = 1; s < SEGS; s++) {
        float4 t = ((const float4*)g_op[s])[i];
        a.x += t.x; a.y += t.y; a.z += t.z; a.w += t.w;
    }
    ((float4*)g_o)[i] = a;
}

// ---------------------------------------------------------------------------
// K6: output 1x1 conv
// ---------------------------------------------------------------------------
__global__ __launch_bounds__(256) void k_oconv(
    const float* __restrict__ Wo, const float* __restrict__ bo,
    float* __restrict__ out)
{
    __shared__ __align__(16) float sW[64*64];
    __shared__ float sb[64];
    const int tid = threadIdx.x;
    for (int i = tid; i < 4096; i += 256) sW[i] = Wo[i];
    if (tid < 64) sb[tid] = bo[tid];
    __syncthreads();

    const int col = blockIdx.x * 32 + (tid & 31);
    const int og  = tid >> 5;
    const int b   = col / LL;
    const int l   = col - b * LL;

    const float* xp = g_o + (size_t)b * CH * LL + l;
    float xr[64];
#pragma unroll
    for (int c = 0; c < 64; c++) xr[c] = xp[c * LL];

#pragma unroll
    for (int j = 0; j < 8; j++) {
        const int o = og * 8 + j;
        const float4* wr = (const float4*)&sW[o * 64];
        float a0 = 0.f, a1 = 0.f, a2 = 0.f, a3 = 0.f;
#pragma unroll
        for (int c4 = 0; c4 < 16; c4++) {
            float4 w = wr[c4];
            a0 = fmaf(w.x, xr[c4*4+0], a0);
            a1 = fmaf(w.y, xr[c4*4+1], a1);
            a2 = fmaf(w.z, xr[c4*4+2], a2);
            a3 = fmaf(w.w, xr[c4*4+3], a3);
        }
        out[((size_t)b * CH + o) * LL + l] = (a0 + a1) + (a2 + a3) + sb[o];
    }
}

// ---------------------------------------------------------------------------
extern "C" void kernel_launch(void* const* d_in, const int* in_sizes, int n_in,
                              void* d_out, int out_size)
{
    const float* x  = (const float*)d_in[0];
    const float* Wq = (const float*)d_in[1];
    const float* bq = (const float*)d_in[2];
    const float* Wk = (const float*)d_in[3];
    const float* bk = (const float*)d_in[4];
    const float* Wv = (const float*)d_in[5];
    const float* bv = (const float*)d_in[6];
    const float* Wo = (const float*)d_in[7];
    const float* bo = (const float*)d_in[8];

    float* out   = (float*)d_out;           // first output: conv result
    float* q_out = (float*)d_out + BCHL;    // second output: scaled q

    k_qkv<<<144, 256>>>(x, Wq, bq, Wk, bk, Wv, bv, q_out);
    k_passA<<<dim3(16, 2, SEGS), 288>>>();
    k_scaleV<<<144, 256>>>();
    k_passB<<<dim3(16, 2, SEGS), 288>>>();
    k_reduce<<<288, 256>>>();
    k_oconv<<<144, 256>>>(Wo, bo, out);
}

// round 3
// speedup vs baseline: 2.0703x; 1.0845x over previous
#include <cuda_runtime.h>

// Problem constants (fixed by the reference setup)
#define BB   2
#define CH   64
#define NH   8
#define DH   8
#define HW   48
#define LL   2304            // HW*HW
#define BCHL (BB*CH*LL)      // 294912
#define SEGS 16
#define QSEG 144             // LL/SEGS
#define KSEG 144

#define LOG2E 1.4426950408889634f

// Packed f32x2 helpers (sm_103a FFMA2 path)
#define FMA2(d,a,b,c) asm("fma.rn.f32x2 %0,%1,%2,%3;" : "=l"(d) : "l"(a), "l"(b), "l"(c))
#define MUL2(d,a,b)   asm("mul.rn.f32x2 %0,%1,%2;"    : "=l"(d) : "l"(a), "l"(b))
#define ADD2(d,a,b)   asm("add.rn.f32x2 %0,%1,%2;"    : "=l"(d) : "l"(a), "l"(b))
#define PACK2(d,x,y)  asm("mov.b64 %0,{%1,%2};"        : "=l"(d) : "f"(x), "f"(y))
#define UNPACK2(x,y,d) asm("mov.b64 {%0,%1},%2;"       : "=f"(x), "=f"(y) : "l"(d))
#define EX2F(r,x)     asm("ex2.approx.ftz.f32 %0,%1;"  : "=f"(r) : "f"(x))

typedef unsigned long long u64;

// Scratch (device globals — no allocation allowed)
__device__ float g_q [BCHL];          // q * d^-0.5 * log2(e)  (for EX2)
__device__ float g_k [BCHL];
__device__ float g_vp[BCHL];          // v, then scaled in-place by 1/Z
__device__ float g_o [BCHL];
__device__ float g_Z [SEGS][BB*NH][LL];
__device__ float g_op[SEGS][BCHL];

// ---------------------------------------------------------------------------
// K1: fused q/k/v 1x1 convs.  grid = 288 blocks x 256 thr.
// Block: 16 columns; lane = tid&15 -> column, og = tid>>4 -> 4 out rows.
// ---------------------------------------------------------------------------
__global__ __launch_bounds__(256) void k_qkv(
    const float* __restrict__ x,
    const float* __restrict__ Wq, const float* __restrict__ bq,
    const float* __restrict__ Wk, const float* __restrict__ bk,
    const float* __restrict__ Wv, const float* __restrict__ bv,
    float* __restrict__ q_out)
{
    __shared__ __align__(16) float sW[3][64*64];
    __shared__ float sb[3][64];
    const int tid = threadIdx.x;
    for (int i = tid; i < 4096; i += 256) {
        sW[0][i] = Wq[i]; sW[1][i] = Wk[i]; sW[2][i] = Wv[i];
    }
    if (tid < 64) { sb[0][tid] = bq[tid]; sb[1][tid] = bk[tid]; sb[2][tid] = bv[tid]; }
    __syncthreads();

    const int col = blockIdx.x * 16 + (tid & 15);     // 0..4607
    const int og  = tid >> 4;                          // 0..15
    const int b   = col / LL;
    const int l   = col - b * LL;

    const float* xp = x + (size_t)b * CH * LL + l;
    float xr[64];
#pragma unroll
    for (int c = 0; c < 64; c++) xr[c] = xp[c * LL];

    const float qscale = 0.35355339059327373f;  // 8^-0.5

#pragma unroll
    for (int m = 0; m < 3; m++) {
        float* dst = (m == 0) ? g_q : (m == 1) ? g_k : g_vp;
#pragma unroll
        for (int j = 0; j < 4; j++) {
            const int o = og * 4 + j;
            const float4* wr = (const float4*)&sW[m][o * 64];
            float a0 = 0.f, a1 = 0.f, a2 = 0.f, a3 = 0.f;
#pragma unroll
            for (int c4 = 0; c4 < 16; c4++) {
                float4 w = wr[c4];
                a0 = fmaf(w.x, xr[c4*4+0], a0);
                a1 = fmaf(w.y, xr[c4*4+1], a1);
                a2 = fmaf(w.z, xr[c4*4+2], a2);
                a3 = fmaf(w.w, xr[c4*4+3], a3);
            }
            float r = (a0 + a1) + (a2 + a3) + sb[m][o];
            const size_t idx = ((size_t)b * CH + o) * LL + l;
            if (m == 0) {
                float rq = r * qscale;
                q_out[idx] = rq;                 // reference returns the SCALED q
                dst[idx]   = rq * LOG2E;         // internal: prescaled for EX2
            } else {
                dst[idx] = r;
            }
        }
    }
}

// ---------------------------------------------------------------------------
// K2 (pass A): partial Z over a q-segment.  Each thread owns 4 k columns,
// packed as 2 f32x2 pairs. Q rows stored DUPLICATED in SMEM so the whole
// dot-product chain is packed FFMA2.
// grid = (bh=16, ktile=2, seg=16) x 288 thr.
// ---------------------------------------------------------------------------
__global__ __launch_bounds__(288) void k_passA()
{
    const int bh = blockIdx.x;
    const int b = bh >> 3, h = bh & 7;
    const int tid = threadIdx.x;
    const int k0 = blockIdx.y * 1152 + tid * 4;
    const int seg = blockIdx.z;

    const float* Kb = g_k + (size_t)(b * CH + h * DH) * LL;
    const float* Qb = g_q + (size_t)(b * CH + h * DH) * LL;

    u64 kp0[8], kp1[8];
#pragma unroll
    for (int d = 0; d < 8; d++) {
        float4 kv = *(const float4*)&Kb[d * LL + k0];
        PACK2(kp0[d], kv.x, kv.y);
        PACK2(kp1[d], kv.z, kv.w);
    }

    __shared__ __align__(16) float2 sq[QSEG][8];
    const int q0 = seg * QSEG;
    for (int i = tid; i < QSEG * 8; i += 288) {
        const int d = i / QSEG, qq = i - d * QSEG;
        float v = Qb[d * LL + q0 + qq];
        sq[qq][d] = make_float2(v, v);
    }
    __syncthreads();

    u64 Z0 = 0ull, Z1 = 0ull;   // packed {0,0}
#pragma unroll 2
    for (int qq = 0; qq < QSEG; qq++) {
        const ulonglong2* qr = (const ulonglong2*)sq[qq];
        ulonglong2 qa = qr[0], qb_ = qr[1], qc = qr[2], qd = qr[3];
        u64 l0, l1;
        MUL2(l0, qa.x,  kp0[0]); FMA2(l0, qa.y,  kp0[1], l0);
        FMA2(l0, qb_.x, kp0[2], l0); FMA2(l0, qb_.y, kp0[3], l0);
        FMA2(l0, qc.x,  kp0[4], l0); FMA2(l0, qc.y,  kp0[5], l0);
        FMA2(l0, qd.x,  kp0[6], l0); FMA2(l0, qd.y,  kp0[7], l0);
        MUL2(l1, qa.x,  kp1[0]); FMA2(l1, qa.y,  kp1[1], l1);
        FMA2(l1, qb_.x, kp1[2], l1); FMA2(l1, qb_.y, kp1[3], l1);
        FMA2(l1, qc.x,  kp1[4], l1); FMA2(l1, qc.y,  kp1[5], l1);
        FMA2(l1, qd.x,  kp1[6], l1); FMA2(l1, qd.y,  kp1[7], l1);
        float a0, a1, b0, b1, e0, e1, e2, e3;
        UNPACK2(a0, a1, l0);
        UNPACK2(b0, b1, l1);
        EX2F(e0, a0); EX2F(e1, a1); EX2F(e2, b0); EX2F(e3, b1);
        u64 w0, w1;
        PACK2(w0, e0, e1);
        PACK2(w1, e2, e3);
        ADD2(Z0, Z0, w0);
        ADD2(Z1, Z1, w1);
    }
    float z0, z1, z2, z3;
    UNPACK2(z0, z1, Z0);
    UNPACK2(z2, z3, Z1);
    *(float4*)&g_Z[seg][bh][k0] = make_float4(z0, z1, z2, z3);
}

// ---------------------------------------------------------------------------
// K3: sum Z partials, scale v by 1/Z.  One thread per k column.
// ---------------------------------------------------------------------------
__global__ __launch_bounds__(256) void k_scaleV()
{
    const int t = blockIdx.x * 256 + threadIdx.x;  // 0..36863
    const int bh = t / LL, k = t - bh * LL;
    float z = 0.f;
#pragma unroll
    for (int s = 0; s < SEGS; s++) z += g_Z[s][bh][k];
    const float inv = 1.0f / z;
    const int b = bh >> 3, h = bh & 7;
    float* Vb = g_vp + (size_t)(b * CH + h * DH) * LL + k;
#pragma unroll
    for (int d = 0; d < 8; d++) Vb[d * LL] *= inv;
}

// ---------------------------------------------------------------------------
// K4 (pass B): partial o over a k-segment.  Each thread owns 4 q columns
// (2 packed pairs).  K and V' rows stored DUPLICATED in SMEM; logit chain
// and output accumulation are all packed FFMA2.
// grid = (bh=16, qtile=2, seg=16) x 288 thr.
// ---------------------------------------------------------------------------
__global__ __launch_bounds__(288) void k_passB()
{
    const int bh = blockIdx.x;
    const int b = bh >> 3, h = bh & 7;
    const int tid = threadIdx.x;
    const int q0 = blockIdx.y * 1152 + tid * 4;
    const int seg = blockIdx.z;

    const float* Qb = g_q  + (size_t)(b * CH + h * DH) * LL;
    const float* Kb = g_k  + (size_t)(b * CH + h * DH) * LL;
    const float* Vb = g_vp + (size_t)(b * CH + h * DH) * LL;

    u64 qp0[8], qp1[8];
#pragma unroll
    for (int d = 0; d < 8; d++) {
        float4 qv = *(const float4*)&Qb[d * LL + q0];
        PACK2(qp0[d], qv.x, qv.y);
        PACK2(qp1[d], qv.z, qv.w);
    }

    __shared__ __align__(16) float2 sk[KSEG][8];
    __shared__ __align__(16) float2 sv[KSEG][8];
    const int kb = seg * KSEG;
    for (int i = tid; i < KSEG * 8; i += 288) {
        const int d = i / KSEG, kk = i - d * KSEG;
        float kval = Kb[d * LL + kb + kk];
        float vval = Vb[d * LL + kb + kk];
        sk[kk][d] = make_float2(kval, kval);
        sv[kk][d] = make_float2(vval, vval);
    }
    __syncthreads();

    u64 o0[8], o1[8];
#pragma unroll
    for (int d = 0; d < 8; d++) { o0[d] = 0ull; o1[d] = 0ull; }

#pragma unroll 2
    for (int kk = 0; kk < KSEG; kk++) {
        const ulonglong2* kr = (const ulonglong2*)sk[kk];
        ulonglong2 ka = kr[0], kb_ = kr[1], kc = kr[2], kd = kr[3];
        u64 l0, l1;
        MUL2(l0, qp0[0], ka.x);  FMA2(l0, qp0[1], ka.y,  l0);
        FMA2(l0, qp0[2], kb_.x, l0); FMA2(l0, qp0[3], kb_.y, l0);
        FMA2(l0, qp0[4], kc.x,  l0); FMA2(l0, qp0[5], kc.y,  l0);
        FMA2(l0, qp0[6], kd.x,  l0); FMA2(l0, qp0[7], kd.y,  l0);
        MUL2(l1, qp1[0], ka.x);  FMA2(l1, qp1[1], ka.y,  l1);
        FMA2(l1, qp1[2], kb_.x, l1); FMA2(l1, qp1[3], kb_.y, l1);
        FMA2(l1, qp1[4], kc.x,  l1); FMA2(l1, qp1[5], kc.y,  l1);
        FMA2(l1, qp1[6], kd.x,  l1); FMA2(l1, qp1[7], kd.y,  l1);
        float a0, a1, b0, b1, e0, e1, e2, e3;
        UNPACK2(a0, a1, l0);
        UNPACK2(b0, b1, l1);
        EX2F(e0, a0); EX2F(e1, a1); EX2F(e2, b0); EX2F(e3, b1);
        u64 w0, w1;
        PACK2(w0, e0, e1);
        PACK2(w1, e2, e3);
        const ulonglong2* vr = (const ulonglong2*)sv[kk];
        ulonglong2 va = vr[0], vb_ = vr[1], vc = vr[2], vd = vr[3];
        FMA2(o0[0], w0, va.x,  o0[0]); FMA2(o1[0], w1, va.x,  o1[0]);
        FMA2(o0[1], w0, va.y,  o0[1]); FMA2(o1[1], w1, va.y,  o1[1]);
        FMA2(o0[2], w0, vb_.x, o0[2]); FMA2(o1[2], w1, vb_.x, o1[2]);
        FMA2(o0[3], w0, vb_.y, o0[3]); FMA2(o1[3], w1, vb_.y, o1[3]);
        FMA2(o0[4], w0, vc.x,  o0[4]); FMA2(o1[4], w1, vc.x,  o1[4]);
        FMA2(o0[5], w0, vc.y,  o0[5]); FMA2(o1[5], w1, vc.y,  o1[5]);
        FMA2(o0[6], w0, vd.x,  o0[6]); FMA2(o1[6], w1, vd.x,  o1[6]);
        FMA2(o0[7], w0, vd.y,  o0[7]); FMA2(o1[7], w1, vd.y,  o1[7]);
    }

    float* Ob = g_op[seg] + (size_t)(b * CH + h * DH) * LL;
#pragma unroll
    for (int d = 0; d < 8; d++) {
        float x0, x1, x2, x3;
        UNPACK2(x0, x1, o0[d]);
        UNPACK2(x2, x3, o1[d]);
        *(float4*)&Ob[d * LL + q0] = make_float4(x0, x1, x2, x3);
    }
}

// ---------------------------------------------------------------------------
// K5: reduce o partials across the 16 k-segments.
// ---------------------------------------------------------------------------
__global__ __launch_bounds__(256) void k_reduce()
{
    const int i = blockIdx.x * 256 + threadIdx.x;  // over BCHL/4 = 73728
    float4 a = ((const float4*)g_op[0])[i];
#pragma unroll
    for (int s = 1; s < SEGS; s++) {
        float4 t = ((const float4*)g_op[s])[i];
        a.x += t.x; a.y += t.y; a.z += t.z; a.w += t.w;
    }
    ((float4*)g_o)[i] = a;
}

// ---------------------------------------------------------------------------
// K6: output 1x1 conv.  grid = 288 blocks x 256 thr (16 cols, 4 rows/group).
// ---------------------------------------------------------------------------
__global__ __launch_bounds__(256) void k_oconv(
    const float* __restrict__ Wo, const float* __restrict__ bo,
    float* __restrict__ out)
{
    __shared__ __align__(16) float sW[64*64];
    __shared__ float sb[64];
    const int tid = threadIdx.x;
    for (int i = tid; i < 4096; i += 256) sW[i] = Wo[i];
    if (tid < 64) sb[tid] = bo[tid];
    __syncthreads();

    const int col = blockIdx.x * 16 + (tid & 15);
    const int og  = tid >> 4;
    const int b   = col / LL;
    const int l   = col - b * LL;

    const float* xp = g_o + (size_t)b * CH * LL + l;
    float xr[64];
#pragma unroll
    for (int c = 0; c < 64; c++) xr[c] = xp[c * LL];

#pragma unroll
    for (int j = 0; j < 4; j++) {
        const int o = og * 4 + j;
        const float4* wr = (const float4*)&sW[o * 64];
        float a0 = 0.f, a1 = 0.f, a2 = 0.f, a3 = 0.f;
#pragma unroll
        for (int c4 = 0; c4 < 16; c4++) {
            float4 w = wr[c4];
            a0 = fmaf(w.x, xr[c4*4+0], a0);
            a1 = fmaf(w.y, xr[c4*4+1], a1);
            a2 = fmaf(w.z, xr[c4*4+2], a2);
            a3 = fmaf(w.w, xr[c4*4+3], a3);
        }
        out[((size_t)b * CH + o) * LL + l] = (a0 + a1) + (a2 + a3) + sb[o];
    }
}

// ---------------------------------------------------------------------------
extern "C" void kernel_launch(void* const* d_in, const int* in_sizes, int n_in,
                              void* d_out, int out_size)
{
    const float* x  = (const float*)d_in[0];
    const float* Wq = (const float*)d_in[1];
    const float* bq = (const float*)d_in[2];
    const float* Wk = (const float*)d_in[3];
    const float* bk = (const float*)d_in[4];
    const float* Wv = (const float*)d_in[5];
    const float* bv = (const float*)d_in[6];
    const float* Wo = (const float*)d_in[7];
    const float* bo = (const float*)d_in[8];

    float* out   = (float*)d_out;           // first output: conv result
    float* q_out = (float*)d_out + BCHL;    // second output: scaled q

    k_qkv<<<288, 256>>>(x, Wq, bq, Wk, bk, Wv, bv, q_out);
    k_passA<<<dim3(16, 2, SEGS), 288>>>();
    k_scaleV<<<144, 256>>>();
    k_passB<<<dim3(16, 2, SEGS), 288>>>();
    k_reduce<<<288, 256>>>();
    k_oconv<<<288, 256>>>(Wo, bo, out);
}

// round 4
// speedup vs baseline: 2.0926x; 1.0108x over previous
#include <cuda_runtime.h>

// Problem constants (fixed by the reference setup)
#define BB   2
#define CH   64
#define NH   8
#define DH   8
#define HW   48
#define LL   2304            // HW*HW
#define BCHL (BB*CH*LL)      // 294912
#define SEGS 9
#define QSEG 256             // LL/SEGS
#define KSEG 256

#define LOG2E 1.4426950408889634f

// Packed f32x2 helpers (sm_103a FFMA2 path)
#define FMA2(d,a,b,c) asm("fma.rn.f32x2 %0,%1,%2,%3;" : "=l"(d) : "l"(a), "l"(b), "l"(c))
#define MUL2(d,a,b)   asm("mul.rn.f32x2 %0,%1,%2;"    : "=l"(d) : "l"(a), "l"(b))
#define ADD2(d,a,b)   asm("add.rn.f32x2 %0,%1,%2;"    : "=l"(d) : "l"(a), "l"(b))
#define PACK2(d,x,y)  asm("mov.b64 %0,{%1,%2};"        : "=l"(d) : "f"(x), "f"(y))
#define UNPACK2(x,y,d) asm("mov.b64 {%0,%1},%2;"       : "=f"(x), "=f"(y) : "l"(d))
#define EX2F(r,x)     asm("ex2.approx.ftz.f32 %0,%1;"  : "=f"(r) : "f"(x))

typedef unsigned long long u64;

// Scratch (device globals — no allocation allowed)
__device__ float g_q [BCHL];          // q * d^-0.5 * log2(e)  (for EX2)
__device__ float g_k [BCHL];
__device__ float g_v [BCHL];
__device__ float g_o [BCHL];
__device__ float g_Z [SEGS][BB*NH][LL];
__device__ float g_zinv[BB*NH*LL];
__device__ float g_op[SEGS][BCHL];

// ---------------------------------------------------------------------------
// K1: fused q/k/v 1x1 convs.  grid = 288 blocks x 256 thr.
// ---------------------------------------------------------------------------
__global__ __launch_bounds__(256) void k_qkv(
    const float* __restrict__ x,
    const float* __restrict__ Wq, const float* __restrict__ bq,
    const float* __restrict__ Wk, const float* __restrict__ bk,
    const float* __restrict__ Wv, const float* __restrict__ bv,
    float* __restrict__ q_out)
{
    __shared__ __align__(16) float sW[3][64*64];
    __shared__ float sb[3][64];
    const int tid = threadIdx.x;
    for (int i = tid; i < 4096; i += 256) {
        sW[0][i] = Wq[i]; sW[1][i] = Wk[i]; sW[2][i] = Wv[i];
    }
    if (tid < 64) { sb[0][tid] = bq[tid]; sb[1][tid] = bk[tid]; sb[2][tid] = bv[tid]; }
    __syncthreads();

    const int col = blockIdx.x * 16 + (tid & 15);     // 0..4607
    const int og  = tid >> 4;                          // 0..15
    const int b   = col / LL;
    const int l   = col - b * LL;

    const float* xp = x + (size_t)b * CH * LL + l;
    float xr[64];
#pragma unroll
    for (int c = 0; c < 64; c++) xr[c] = xp[c * LL];

    const float qscale = 0.35355339059327373f;  // 8^-0.5

#pragma unroll
    for (int m = 0; m < 3; m++) {
        float* dst = (m == 0) ? g_q : (m == 1) ? g_k : g_v;
#pragma unroll
        for (int j = 0; j < 4; j++) {
            const int o = og * 4 + j;
            const float4* wr = (const float4*)&sW[m][o * 64];
            float a0 = 0.f, a1 = 0.f, a2 = 0.f, a3 = 0.f;
#pragma unroll
            for (int c4 = 0; c4 < 16; c4++) {
                float4 w = wr[c4];
                a0 = fmaf(w.x, xr[c4*4+0], a0);
                a1 = fmaf(w.y, xr[c4*4+1], a1);
                a2 = fmaf(w.z, xr[c4*4+2], a2);
                a3 = fmaf(w.w, xr[c4*4+3], a3);
            }
            float r = (a0 + a1) + (a2 + a3) + sb[m][o];
            const size_t idx = ((size_t)b * CH + o) * LL + l;
            if (m == 0) {
                float rq = r * qscale;
                q_out[idx] = rq;                 // reference returns the SCALED q
                dst[idx]   = rq * LOG2E;         // internal: prescaled for EX2
            } else {
                dst[idx] = r;
            }
        }
    }
}

// ---------------------------------------------------------------------------
// K2 (pass A): partial Z over a q-segment.  Each thread owns 4 k columns,
// packed as 2 f32x2 pairs.  grid = (bh=16, ktile=2, seg=9) x 288 thr = 288 blk.
// ---------------------------------------------------------------------------
__global__ __launch_bounds__(288) void k_passA()
{
    const int bh = blockIdx.x;
    const int b = bh >> 3, h = bh & 7;
    const int tid = threadIdx.x;
    const int k0 = blockIdx.y * 1152 + tid * 4;
    const int seg = blockIdx.z;

    const float* Kb = g_k + (size_t)(b * CH + h * DH) * LL;
    const float* Qb = g_q + (size_t)(b * CH + h * DH) * LL;

    u64 kp0[8], kp1[8];
#pragma unroll
    for (int d = 0; d < 8; d++) {
        float4 kv = *(const float4*)&Kb[d * LL + k0];
        PACK2(kp0[d], kv.x, kv.y);
        PACK2(kp1[d], kv.z, kv.w);
    }

    __shared__ __align__(16) float2 sq[QSEG][8];
    const int q0 = seg * QSEG;
    for (int i = tid; i < QSEG * 8; i += 288) {
        const int d = i >> 8, qq = i & 255;
        float v = Qb[d * LL + q0 + qq];
        sq[qq][d] = make_float2(v, v);
    }
    __syncthreads();

    u64 Z0 = 0ull, Z1 = 0ull;   // packed {0,0}
#pragma unroll 2
    for (int qq = 0; qq < QSEG; qq++) {
        const ulonglong2* qr = (const ulonglong2*)sq[qq];
        ulonglong2 qa = qr[0], qb_ = qr[1], qc = qr[2], qd = qr[3];
        u64 l0, l1;
        MUL2(l0, qa.x,  kp0[0]); FMA2(l0, qa.y,  kp0[1], l0);
        FMA2(l0, qb_.x, kp0[2], l0); FMA2(l0, qb_.y, kp0[3], l0);
        FMA2(l0, qc.x,  kp0[4], l0); FMA2(l0, qc.y,  kp0[5], l0);
        FMA2(l0, qd.x,  kp0[6], l0); FMA2(l0, qd.y,  kp0[7], l0);
        MUL2(l1, qa.x,  kp1[0]); FMA2(l1, qa.y,  kp1[1], l1);
        FMA2(l1, qb_.x, kp1[2], l1); FMA2(l1, qb_.y, kp1[3], l1);
        FMA2(l1, qc.x,  kp1[4], l1); FMA2(l1, qc.y,  kp1[5], l1);
        FMA2(l1, qd.x,  kp1[6], l1); FMA2(l1, qd.y,  kp1[7], l1);
        float a0, a1, b0, b1, e0, e1, e2, e3;
        UNPACK2(a0, a1, l0);
        UNPACK2(b0, b1, l1);
        EX2F(e0, a0); EX2F(e1, a1); EX2F(e2, b0); EX2F(e3, b1);
        u64 w0, w1;
        PACK2(w0, e0, e1);
        PACK2(w1, e2, e3);
        ADD2(Z0, Z0, w0);
        ADD2(Z1, Z1, w1);
    }
    float z0, z1, z2, z3;
    UNPACK2(z0, z1, Z0);
    UNPACK2(z2, z3, Z1);
    *(float4*)&g_Z[seg][bh][k0] = make_float4(z0, z1, z2, z3);
}

// ---------------------------------------------------------------------------
// K3: sum Z partials -> 1/Z per (bh, k).  36864 threads.
// ---------------------------------------------------------------------------
__global__ __launch_bounds__(256) void k_zsum()
{
    const int t = blockIdx.x * 256 + threadIdx.x;  // 0..36863 == bh*LL + k
    float z = 0.f;
#pragma unroll
    for (int s = 0; s < SEGS; s++) z += g_Z[0][0][(size_t)s * (BB*NH) * LL + t];
    g_zinv[t] = 1.0f / z;
}

// ---------------------------------------------------------------------------
// K4 (pass B): partial o over a k-segment.  Each thread owns 4 q columns.
// V is scaled by 1/Z during the SMEM fill (scaleV fused here).
// grid = (bh=16, qtile=2, seg=9) x 288 thr = 288 blocks (single wave).
// ---------------------------------------------------------------------------
__global__ __launch_bounds__(288) void k_passB()
{
    const int bh = blockIdx.x;
    const int b = bh >> 3, h = bh & 7;
    const int tid = threadIdx.x;
    const int q0 = blockIdx.y * 1152 + tid * 4;
    const int seg = blockIdx.z;

    const float* Qb = g_q + (size_t)(b * CH + h * DH) * LL;
    const float* Kb = g_k + (size_t)(b * CH + h * DH) * LL;
    const float* Vb = g_v + (size_t)(b * CH + h * DH) * LL;
    const float* Zi = g_zinv + (size_t)bh * LL;

    u64 qp0[8], qp1[8];
#pragma unroll
    for (int d = 0; d < 8; d++) {
        float4 qv = *(const float4*)&Qb[d * LL + q0];
        PACK2(qp0[d], qv.x, qv.y);
        PACK2(qp1[d], qv.z, qv.w);
    }

    __shared__ __align__(16) float2 sk[KSEG][8];
    __shared__ __align__(16) float2 sv[KSEG][8];
    const int kb = seg * KSEG;
    for (int i = tid; i < KSEG * 8; i += 288) {
        const int d = i >> 8, kk = i & 255;
        float kval = Kb[d * LL + kb + kk];
        float vval = Vb[d * LL + kb + kk] * Zi[kb + kk];
        sk[kk][d] = make_float2(kval, kval);
        sv[kk][d] = make_float2(vval, vval);
    }
    __syncthreads();

    u64 o0[8], o1[8];
#pragma unroll
    for (int d = 0; d < 8; d++) { o0[d] = 0ull; o1[d] = 0ull; }

#pragma unroll 2
    for (int kk = 0; kk < KSEG; kk++) {
        const ulonglong2* kr = (const ulonglong2*)sk[kk];
        ulonglong2 ka = kr[0], kb_ = kr[1], kc = kr[2], kd = kr[3];
        u64 l0, l1;
        MUL2(l0, qp0[0], ka.x);  FMA2(l0, qp0[1], ka.y,  l0);
        FMA2(l0, qp0[2], kb_.x, l0); FMA2(l0, qp0[3], kb_.y, l0);
        FMA2(l0, qp0[4], kc.x,  l0); FMA2(l0, qp0[5], kc.y,  l0);
        FMA2(l0, qp0[6], kd.x,  l0); FMA2(l0, qp0[7], kd.y,  l0);
        MUL2(l1, qp1[0], ka.x);  FMA2(l1, qp1[1], ka.y,  l1);
        FMA2(l1, qp1[2], kb_.x, l1); FMA2(l1, qp1[3], kb_.y, l1);
        FMA2(l1, qp1[4], kc.x,  l1); FMA2(l1, qp1[5], kc.y,  l1);
        FMA2(l1, qp1[6], kd.x,  l1); FMA2(l1, qp1[7], kd.y,  l1);
        float a0, a1, b0, b1, e0, e1, e2, e3;
        UNPACK2(a0, a1, l0);
        UNPACK2(b0, b1, l1);
        EX2F(e0, a0); EX2F(e1, a1); EX2F(e2, b0); EX2F(e3, b1);
        u64 w0, w1;
        PACK2(w0, e0, e1);
        PACK2(w1, e2, e3);
        const ulonglong2* vr = (const ulonglong2*)sv[kk];
        ulonglong2 va = vr[0], vb_ = vr[1], vc = vr[2], vd = vr[3];
        FMA2(o0[0], w0, va.x,  o0[0]); FMA2(o1[0], w1, va.x,  o1[0]);
        FMA2(o0[1], w0, va.y,  o0[1]); FMA2(o1[1], w1, va.y,  o1[1]);
        FMA2(o0[2], w0, vb_.x, o0[2]); FMA2(o1[2], w1, vb_.x, o1[2]);
        FMA2(o0[3], w0, vb_.y, o0[3]); FMA2(o1[3], w1, vb_.y, o1[3]);
        FMA2(o0[4], w0, vc.x,  o0[4]); FMA2(o1[4], w1, vc.x,  o1[4]);
        FMA2(o0[5], w0, vc.y,  o0[5]); FMA2(o1[5], w1, vc.y,  o1[5]);
        FMA2(o0[6], w0, vd.x,  o0[6]); FMA2(o1[6], w1, vd.x,  o1[6]);
        FMA2(o0[7], w0, vd.y,  o0[7]); FMA2(o1[7], w1, vd.y,  o1[7]);
    }

    float* Ob = g_op[seg] + (size_t)(b * CH + h * DH) * LL;
#pragma unroll
    for (int d = 0; d < 8; d++) {
        float x0, x1, x2, x3;
        UNPACK2(x0, x1, o0[d]);
        UNPACK2(x2, x3, o1[d]);
        *(float4*)&Ob[d * LL + q0] = make_float4(x0, x1, x2, x3);
    }
}

// ---------------------------------------------------------------------------
// K5: reduce o partials across the 9 k-segments.
// ---------------------------------------------------------------------------
__global__ __launch_bounds__(256) void k_reduce()
{
    const int i = blockIdx.x * 256 + threadIdx.x;  // over BCHL/4 = 73728
    float4 a = ((const float4*)g_op[0])[i];
#pragma unroll
    for (int s = 1; s < SEGS; s++) {
        float4 t = ((const float4*)g_op[s])[i];
        a.x += t.x; a.y += t.y; a.z += t.z; a.w += t.w;
    }
    ((float4*)g_o)[i] = a;
}

// ---------------------------------------------------------------------------
// K6: output 1x1 conv.  grid = 288 blocks x 256 thr.
// ---------------------------------------------------------------------------
__global__ __launch_bounds__(256) void k_oconv(
    const float* __restrict__ Wo, const float* __restrict__ bo,
    float* __restrict__ out)
{
    __shared__ __align__(16) float sW[64*64];
    __shared__ float sb[64];
    const int tid = threadIdx.x;
    for (int i = tid; i < 4096; i += 256) sW[i] = Wo[i];
    if (tid < 64) sb[tid] = bo[tid];
    __syncthreads();

    const int col = blockIdx.x * 16 + (tid & 15);
    const int og  = tid >> 4;
    const int b   = col / LL;
    const int l   = col - b * LL;

    const float* xp = g_o + (size_t)b * CH * LL + l;
    float xr[64];
#pragma unroll
    for (int c = 0; c < 64; c++) xr[c] = xp[c * LL];

#pragma unroll
    for (int j = 0; j < 4; j++) {
        const int o = og * 4 + j;
        const float4* wr = (const float4*)&sW[o * 64];
        float a0 = 0.f, a1 = 0.f, a2 = 0.f, a3 = 0.f;
#pragma unroll
        for (int c4 = 0; c4 < 16; c4++) {
            float4 w = wr[c4];
            a0 = fmaf(w.x, xr[c4*4+0], a0);
            a1 = fmaf(w.y, xr[c4*4+1], a1);
            a2 = fmaf(w.z, xr[c4*4+2], a2);
            a3 = fmaf(w.w, xr[c4*4+3], a3);
        }
        out[((size_t)b * CH + o) * LL + l] = (a0 + a1) + (a2 + a3) + sb[o];
    }
}

// ---------------------------------------------------------------------------
extern "C" void kernel_launch(void* const* d_in, const int* in_sizes, int n_in,
                              void* d_out, int out_size)
{
    const float* x  = (const float*)d_in[0];
    const float* Wq = (const float*)d_in[1];
    const float* bq = (const float*)d_in[2];
    const float* Wk = (const float*)d_in[3];
    const float* bk = (const float*)d_in[4];
    const float* Wv = (const float*)d_in[5];
    const float* bv = (const float*)d_in[6];
    const float* Wo = (const float*)d_in[7];
    const float* bo = (const float*)d_in[8];

    float* out   = (float*)d_out;           // first output: conv result
    float* q_out = (float*)d_out + BCHL;    // second output: scaled q

    k_qkv<<<288, 256>>>(x, Wq, bq, Wk, bk, Wv, bv, q_out);
    k_passA<<<dim3(16, 2, SEGS), 288>>>();
    k_zsum<<<144, 256>>>();
    k_passB<<<dim3(16, 2, SEGS), 288>>>();
    k_reduce<<<288, 256>>>();
    k_oconv<<<288, 256>>>(Wo, bo, out);
}